// round 5
// baseline (speedup 1.0000x reference)
#include <cuda_runtime.h>
#include <cuda_bf16.h>

#define BB     4
#define NN     8192
#define CC     256
#define POOLN  2048
#define NBR    4
#define TILE_PTS    1024                 // smem vertex tile (first 1024 pts of batch)
#define TILE_FLOATS (TILE_PTS * 3)       // 12 KB
#define QPB    8                         // queries (warps) per block

__device__ __forceinline__ float decode_radius(const int* radius_raw)
{
    const unsigned rv = (unsigned)__ldg(radius_raw);
    return (rv & 0x7F800000u) ? __int_as_float((int)rv) : (float)(int)rv;
}

// Single fused kernel: easy warp-scan over smem tile + in-block cooperative
// full-N rescan for the rare hard queries. One launch, zero global state.
__global__ __launch_bounds__(256)
void pool_fused_kernel(const float* __restrict__ verts,
                       const float* __restrict__ feat,
                       const int*   __restrict__ radius_raw,
                       const int*   __restrict__ sample_idx,
                       float* __restrict__ outV,
                       float* __restrict__ outF)
{
    __shared__ float    s_tile[TILE_FLOATS];
    __shared__ unsigned s_hard;            // bitmask of warps needing full rescan
    __shared__ int      s_wsum[8];
    __shared__ int      s_idx[NBR];
    __shared__ int      s_total;

    const int wid  = threadIdx.x >> 5;
    const int lane = threadIdx.x & 31;
    const int qid  = blockIdx.x * QPB + wid;   // block never straddles batches
    const int b    = qid >> 11;                // / POOLN
    const int s    = qid & (POOLN - 1);

    if (threadIdx.x == 0) s_hard = 0;

    // Cooperative tile load: 768 float4, coalesced.
    {
        const float4* __restrict__ src = (const float4*)(verts + (size_t)b * NN * 3);
        float4* dst = (float4*)s_tile;
        #pragma unroll
        for (int i = 0; i < TILE_FLOATS / 4 / 256; i++)
            dst[threadIdx.x + 256 * i] = src[threadIdx.x + 256 * i];
    }

    const float radius = decode_radius(radius_raw);
    const float r2 = radius * radius;

    const int n = sample_idx[s];
    const float* vb = verts + (size_t)b * NN * 3;
    const float qx = vb[n * 3 + 0];
    const float qy = vb[n * 3 + 1];
    const float qz = vb[n * 3 + 2];
    const float sqn = qx * qx + qy * qy + qz * qz;

    if (lane < 3) {
        const float v = (lane == 0) ? qx : (lane == 1) ? qy : qz;
        outV[((size_t)b * POOLN + s) * 3 + lane] = v;
    }

    __syncthreads();

    // ---- easy scan over smem tile: first NBR ascending qualifiers ----
    int idx[NBR];
    int cnt = 0;
    #pragma unroll
    for (int k = 0; k < NBR; k++) idx[k] = n;

    for (int base = 0; base < TILE_PTS; base += 128) {
        unsigned bal[4];
        #pragma unroll
        for (int t = 0; t < 4; t++) {
            const int p = base + t * 32 + lane;
            const float px = s_tile[3 * p + 0];
            const float py = s_tile[3 * p + 1];
            const float pz = s_tile[3 * p + 2];
            const float d = -2.0f * (px * qx + py * qy + pz * qz) + sqn
                            + (px * px + py * py + pz * pz);
            bal[t] = __ballot_sync(0xFFFFFFFFu, !(d > r2));
        }
        #pragma unroll
        for (int t = 0; t < 4; t++) {
            unsigned m = bal[t];
            while (m && cnt < NBR) {
                idx[cnt++] = base + t * 32 + (__ffs(m) - 1);
                m &= m - 1;
            }
        }
        if (cnt >= NBR) break;   // uniform (ballot-derived)
    }

    const bool hard = (cnt < NBR);
    if (hard) {
        if (lane == 0) atomicOr(&s_hard, 1u << wid);
    } else {
        // gather 4 feature rows, max, store
        const float* fb = feat + (size_t)b * NN * CC;
        const float4* __restrict__ f0 = (const float4*)(fb + (size_t)idx[0] * CC);
        const float4* __restrict__ f1 = (const float4*)(fb + (size_t)idx[1] * CC);
        const float4* __restrict__ f2 = (const float4*)(fb + (size_t)idx[2] * CC);
        const float4* __restrict__ f3 = (const float4*)(fb + (size_t)idx[3] * CC);
        float4* __restrict__ fo = (float4*)(outF + ((size_t)b * POOLN + s) * CC);
        #pragma unroll
        for (int j = 0; j < CC / 128; j++) {
            const int c = lane + j * 32;
            float4 a = f0[c];
            const float4 v1 = f1[c], v2 = f2[c], v3 = f3[c];
            a.x = fmaxf(fmaxf(a.x, v1.x), fmaxf(v2.x, v3.x));
            a.y = fmaxf(fmaxf(a.y, v1.y), fmaxf(v2.y, v3.y));
            a.z = fmaxf(fmaxf(a.z, v1.z), fmaxf(v2.z, v3.z));
            a.w = fmaxf(fmaxf(a.w, v1.w), fmaxf(v2.w, v3.w));
            fo[c] = a;
        }
    }

    __syncthreads();
    unsigned hm = s_hard;                      // uniform across the block

    // ---- cooperative full-N rescan for each hard warp in this block ----
    while (hm) {
        const int hw = __ffs(hm) - 1;
        hm &= hm - 1;

        const int hqid = blockIdx.x * QPB + hw;
        const int hs   = hqid & (POOLN - 1);
        const int hn   = sample_idx[hs];
        const int t    = threadIdx.x;          // owns points [t*32, t*32+32)
        const int tl   = t & 31;
        const int tw   = t >> 5;

        const float hqx = vb[hn * 3 + 0];
        const float hqy = vb[hn * 3 + 1];
        const float hqz = vb[hn * 3 + 2];
        const float hsq = hqx * hqx + hqy * hqy + hqz * hqz;

        // qualify mask over 32 contiguous points (24 coalesced float4 loads)
        unsigned mask = 0;
        const float4* __restrict__ base4 = (const float4*)(vb + (size_t)t * 96);
        #pragma unroll
        for (int g = 0; g < 4; g++) {
            float4 v[6];
            #pragma unroll
            for (int u = 0; u < 6; u++) v[u] = base4[g * 6 + u];
            const float* f = (const float*)v;
            #pragma unroll
            for (int j = 0; j < 8; j++) {
                const float px = f[3 * j + 0];
                const float py = f[3 * j + 1];
                const float pz = f[3 * j + 2];
                const float d = -2.0f * (px * hqx + py * hqy + pz * hqz) + hsq
                                + (px * px + py * py + pz * pz);
                mask |= ((unsigned)(!(d > r2))) << (g * 8 + j);
            }
        }

        // block-wide exclusive prefix over popcounts
        const int c = __popc(mask);
        int x = c;
        #pragma unroll
        for (int o = 1; o < 32; o <<= 1) {
            const int y = __shfl_up_sync(0xFFFFFFFFu, x, o);
            if (tl >= o) x += y;
        }
        if (tl == 31) s_wsum[tw] = x;
        __syncthreads();
        if (t == 0) {
            int acc = 0;
            #pragma unroll
            for (int w = 0; w < 8; w++) { const int v = s_wsum[w]; s_wsum[w] = acc; acc += v; }
            s_total = acc;
        }
        __syncthreads();
        const int pre = s_wsum[tw] + x - c;

        if (mask && pre < NBR) {
            unsigned m = mask;
            int p = pre;
            while (m && p < NBR) {
                s_idx[p++] = t * 32 + (__ffs(m) - 1);
                m &= m - 1;
            }
        }
        __syncthreads();
        if (t == 0) {
            const int tot = s_total < NBR ? s_total : NBR;   // >= 1 (self qualifies)
            for (int k = tot; k < NBR; k++) s_idx[k] = s_idx[0];
        }
        __syncthreads();

        if (t < CC / 4) {
            const float* fb = feat + (size_t)b * NN * CC;
            const float4 a0 = ((const float4*)(fb + (size_t)s_idx[0] * CC))[t];
            const float4 a1 = ((const float4*)(fb + (size_t)s_idx[1] * CC))[t];
            const float4 a2 = ((const float4*)(fb + (size_t)s_idx[2] * CC))[t];
            const float4 a3 = ((const float4*)(fb + (size_t)s_idx[3] * CC))[t];
            float4 r;
            r.x = fmaxf(fmaxf(a0.x, a1.x), fmaxf(a2.x, a3.x));
            r.y = fmaxf(fmaxf(a0.y, a1.y), fmaxf(a2.y, a3.y));
            r.z = fmaxf(fmaxf(a0.z, a1.z), fmaxf(a2.z, a3.z));
            r.w = fmaxf(fmaxf(a0.w, a1.w), fmaxf(a2.w, a3.w));
            ((float4*)(outF + ((size_t)b * POOLN + hs) * CC))[t] = r;
        }
        __syncthreads();   // protect s_* reuse for next hard query
    }
}

extern "C" void kernel_launch(void* const* d_in, const int* in_sizes, int n_in,
                              void* d_out, int out_size)
{
    const float* verts      = (const float*)d_in[0];
    const float* feat       = (const float*)d_in[1];
    const int*   radius_raw = (const int*)  d_in[2];
    const int*   sample_idx = (const int*)  d_in[3];

    float* outV = (float*)d_out;
    float* outF = (float*)d_out + (size_t)BB * POOLN * 3;

    pool_fused_kernel<<<BB * POOLN / QPB, 256>>>(verts, feat, radius_raw,
                                                 sample_idx, outV, outF);
}